// round 1
// baseline (speedup 1.0000x reference)
#include <cuda_runtime.h>

#define NBATCH 32
#define CIN    18
#define HH     256
#define WW     256
#define OC     64
#define TILE   32
#define OCB    16
#define CCHUNK 6

__device__ __forceinline__ unsigned long long pack2(float lo, float hi) {
    unsigned long long r;
    asm("mov.b64 %0, {%1, %2};" : "=l"(r) : "f"(lo), "f"(hi));
    return r;
}
__device__ __forceinline__ float2 unpack2(unsigned long long v) {
    float2 f;
    asm("mov.b64 {%0, %1}, %2;" : "=f"(f.x), "=f"(f.y) : "l"(v));
    return f;
}
// Packed dual fp32 FMA — 2 FMAs/instr on the fma pipe (sm_103a f32x2 path).
__device__ __forceinline__ unsigned long long fma2(unsigned long long a,
                                                   unsigned long long b,
                                                   unsigned long long c) {
    unsigned long long d;
    asm("fma.rn.f32x2 %0, %1, %2, %3;" : "=l"(d) : "l"(a), "l"(b), "l"(c));
    return d;
}

__global__ __launch_bounds__(256, 2)
void conv3x3_f32x2_kernel(const float* __restrict__ x,
                          const float* __restrict__ wgt,
                          const float* __restrict__ bias,
                          float* __restrict__ out) {
    __shared__ float sIn[CCHUNK][34][34];                 // 27744 B
    __shared__ unsigned long long sW[CIN * 9][OCB];       // 20736 B (w duplicated in both halves)

    const int tid     = threadIdx.x;
    const int tileX   = (blockIdx.x & 7) * TILE;
    const int tileY   = (blockIdx.x >> 3) * TILE;
    const int oc_base = blockIdx.y * OCB;
    const int n       = blockIdx.z;

    // Load weights once, duplicated into both f32x2 lanes.
    for (int e = tid; e < CIN * 9 * OCB; e += 256) {
        int k_all = e >> 4;        // c*9 + k, 0..161
        int oc    = e & 15;
        float w   = wgt[(oc_base + oc) * (CIN * 9) + k_all];
        sW[k_all][oc] = pack2(w, w);
    }

    const int tx = (tid & 15) * 2;   // x0 within tile (even -> 8B aligned pairs)
    const int ty = (tid >> 4) * 2;   // y0 within tile

    unsigned long long acc[2][OCB];
    #pragma unroll
    for (int oc = 0; oc < OCB; oc++) {
        float b = bias[oc_base + oc];
        unsigned long long bb = pack2(b, b);
        acc[0][oc] = bb;
        acc[1][oc] = bb;
    }

    #pragma unroll 1
    for (int cc = 0; cc < CIN; cc += CCHUNK) {
        __syncthreads();
        // Stage input chunk (6 channels) with 1-px halo, zero-padded at borders.
        for (int e = tid; e < CCHUNK * 34 * 34; e += 256) {
            int c   = e / (34 * 34);
            int rem = e - c * (34 * 34);
            int yy  = rem / 34;
            int xx  = rem - yy * 34;
            int gy  = tileY + yy - 1;
            int gx  = tileX + xx - 1;
            float v = 0.0f;
            if ((unsigned)gy < HH && (unsigned)gx < WW)
                v = x[((n * CIN + (cc + c)) * HH + gy) * WW + gx];
            sIn[c][yy][xx] = v;
        }
        __syncthreads();

        #pragma unroll 2
        for (int c = 0; c < CCHUNK; c++) {
            #pragma unroll
            for (int ky = 0; ky < 3; ky++) {
                #pragma unroll
                for (int kx = 0; kx < 3; kx++) {
                    unsigned long long a0 =
                        pack2(sIn[c][ty + ky][tx + kx], sIn[c][ty + ky][tx + kx + 1]);
                    unsigned long long a1 =
                        pack2(sIn[c][ty + 1 + ky][tx + kx], sIn[c][ty + 1 + ky][tx + kx + 1]);
                    const unsigned long long* wrow = sW[(cc + c) * 9 + ky * 3 + kx];
                    #pragma unroll
                    for (int oc = 0; oc < OCB; oc++) {
                        unsigned long long w = wrow[oc];
                        acc[0][oc] = fma2(a0, w, acc[0][oc]);
                        acc[1][oc] = fma2(a1, w, acc[1][oc]);
                    }
                }
            }
        }
    }

    // Write 2 rows x 16 oc of float2 pairs (8B-aligned: tx is even).
    #pragma unroll
    for (int oc = 0; oc < OCB; oc++) {
        #pragma unroll
        for (int r = 0; r < 2; r++) {
            float2 v = unpack2(acc[r][oc]);
            long oy = tileY + ty + r;
            long ox = tileX + tx;
            float* p = out + ((((long)n * OC + oc_base + oc) * HH + oy) * WW + ox);
            *reinterpret_cast<float2*>(p) = v;
        }
    }
}

extern "C" void kernel_launch(void* const* d_in, const int* in_sizes, int n_in,
                              void* d_out, int out_size) {
    const float* x    = (const float*)d_in[0];
    const float* wgt  = (const float*)d_in[1];
    const float* bias = (const float*)d_in[2];
    float* out        = (float*)d_out;

    dim3 grid(64 /* 8x8 tiles */, OC / OCB /* 4 */, NBATCH /* 32 */);
    conv3x3_f32x2_kernel<<<grid, 256>>>(x, wgt, bias, out);
}